// round 6
// baseline (speedup 1.0000x reference)
#include <cuda_runtime.h>
#include <cstdint>

// NLCCSCriterion — 128 independent 256x256 masks, one CTA per image.
// R5 (bisect): R4's run-start-only union-find core (Phases A/B/C) + the
// known-good round-4 Phases D/E/F/G verbatim (per-pixel areas/bbox, reload G).

#define HH 256
#define WW 256
#define NPIX (HH * WW)          // 65536
#define NIMG 128
#define NT 1024
#define PPT (NPIX / NT)         // 64
#define NWORDS (NPIX / 32)      // 2048 bitmap words, 8 per row
#define WPT (NWORDS / NT)       // 2 words per thread
#define BGLAB 0x10000u          // sentinel label S = 65536

// smem layout offsets (bytes)
#define OFF_L     0             // uint16 labels[65536]            : 131072
#define OFF_FGW   131072        // uint32 fg bitmap[2048]          : 8192
#define OFF_TOP   139264        // u64 warp top2[64]               : 512
#define OFF_WSF   139776        // float warp sums[32]             : 128
#define OFF_WSI   139904        // int warp sums[32]               : 128
#define OFF_BB    140032        // int bbox[4]                     : 16
#define OFF_MISC  140048        // int misc[2]: [0]=second/flag, [1]=fgtot
#define SMEM_BYTES 140064

__device__ int      g_area[NIMG][NPIX];   // all-zero between calls (rezeroed by owner)
__device__ float    g_loss[NIMG];
__device__ unsigned g_count;

__device__ __forceinline__ unsigned short atomicMinU16(unsigned short* addr, unsigned short val) {
    unsigned short old = *addr;
    while (old > val) {
        unsigned short prev = atomicCAS(addr, old, val);
        if (prev == old) return prev;
        old = prev;
    }
    return old;
}

// path-halving find (lock-free: stores always write ancestors, parents only decrease)
__device__ __forceinline__ unsigned find_halve(unsigned short* L, unsigned a) {
    unsigned short n;
    while ((n = L[a]) != (unsigned short)a) {
        unsigned short nn = L[n];
        L[a] = nn;
        a = nn;
    }
    return a;
}

__device__ __forceinline__ void merge_labels(unsigned short* L, unsigned a, unsigned b) {
    while (true) {
        a = find_halve(L, a);
        b = find_halve(L, b);
        if (a == b) return;
        unsigned hi = a > b ? a : b;
        unsigned lo = a + b - hi;
        unsigned short old = atomicMinU16(&L[hi], (unsigned short)lo);
        if (old == (unsigned short)hi) return;
        a = old;
        b = lo;
    }
}

// run start (within word) of bit j, as a pixel index
__device__ __forceinline__ unsigned rs_of(unsigned word, unsigned basepix, int j) {
    unsigned zb = ~word & ((1u << j) - 1u);
    unsigned rs = zb ? (32u - (unsigned)__clz(zb)) : 0u;
    return basepix + rs;
}

__device__ __forceinline__ void top2_merge(unsigned long long& k1, unsigned long long& k2,
                                           unsigned long long o1, unsigned long long o2) {
    if (o1 > k1) { k2 = (k1 > o2) ? k1 : o2; k1 = o1; }
    else if (o1 > k2) k2 = o1;
}

__global__ __launch_bounds__(NT, 1)
void nlccs_kernel(const float* __restrict__ in, float* __restrict__ out) {
    extern __shared__ unsigned char sraw[];
    unsigned short*      L      = (unsigned short*)(sraw + OFF_L);
    unsigned int*        fgw    = (unsigned int*)(sraw + OFF_FGW);
    unsigned long long*  s_top  = (unsigned long long*)(sraw + OFF_TOP);
    float*               s_wsf  = (float*)(sraw + OFF_WSF);
    int*                 s_wsi  = (int*)(sraw + OFF_WSI);
    int*                 s_bb   = (int*)(sraw + OFF_BB);
    int*                 s_misc = (int*)(sraw + OFF_MISC);

    const int t    = threadIdx.x;
    const int lane = t & 31;          // == p & 31 for p = t + i*NT
    const int warp = t >> 5;
    const int b    = blockIdx.x;
    const float* img  = in + (size_t)b * NPIX;
    int*         area = &g_area[b][0];

    // ---------- Phase A: threshold, bitmap, run-start-only labels ----------
    int fgl = 0;
    #pragma unroll 4
    for (int i = 0; i < PPT; ++i) {
        int p = t + i * NT;
        float x = __ldg(&img[p]);
        float m = fmaxf((x + 1.0f) * 0.5f, 0.0f);    // exact reference arithmetic
        bool fg = m > 0.5f;
        unsigned bal = __ballot_sync(0xFFFFFFFFu, fg);
        if (lane == 0) { fgw[p >> 5] = bal; fgl += __popc(bal); }
        bool isrs = fg && (lane == 0 || !((bal >> (lane - 1)) & 1u));
        if (isrs) L[p] = (unsigned short)p;          // only run-start entries exist
    }
    if (lane == 0) s_wsi[warp] = fgl;                // lane0 holds warp total
    if (t == 0) { s_bb[0] = HH; s_bb[1] = -1; s_bb[2] = WW; s_bb[3] = -1; }
    __syncthreads();
    if (t == 0) {
        int tot = 0;
        #pragma unroll
        for (int w = 0; w < 32; ++w) tot += s_wsi[w];
        s_misc[1] = tot;
    }

    // ---------- Phase B: pruned merges, run-start endpoints ----------
    #pragma unroll
    for (int wi = 0; wi < WPT; ++wi) {
        const int w = t + wi * NT;
        const unsigned cur = fgw[w];
        if (!cur) continue;
        const int wc  = w & 7;
        const int row = w >> 3;
        const unsigned base = (unsigned)w << 5;

        const unsigned prev = (wc > 0) ? fgw[w - 1] : 0u;
        if ((cur & 1u) && (prev >> 31))
            merge_labels(L, base, rs_of(prev, base - 32, 31));   // horizontal boundary

        if (row > 0) {
            const unsigned up    = fgw[w - 8];
            const unsigned upl   = (wc > 0) ? fgw[w - 9] : 0u;
            const unsigned upl31 = upl >> 31;
            const unsigned upr0  = (wc < 7) ? (fgw[w - 7] & 1u) : 0u;
            const unsigned nxt0  = (wc < 7) ? (fgw[w + 1] & 1u) : 0u;

            const unsigned westc = (cur << 1) | (prev >> 31);
            const unsigned westu = (up  << 1) | upl31;
            const unsigned eastc = (cur >> 1) | (nxt0 << 31);
            const unsigned eastu = (up  >> 1) | (upr0 << 31);

            unsigned maskN  = cur & up    & ~(westc & westu);
            unsigned maskNW = cur & westu & ~up & ~westc;
            unsigned maskNE = cur & eastu & ~up & ~eastc;

            const unsigned baseu = base - WW;

            while (maskN)  {
                int j = __ffs(maskN) - 1; maskN &= maskN - 1;
                merge_labels(L, rs_of(cur, base, j), rs_of(up, baseu, j));
            }
            if (maskNW & 1u) {                       // NW of bit0 lives in word w-9
                merge_labels(L, base, rs_of(upl, baseu - 32, 31));
                maskNW &= ~1u;
            }
            while (maskNW) {
                int j = __ffs(maskNW) - 1; maskNW &= maskNW - 1;
                merge_labels(L, rs_of(cur, base, j), rs_of(up, baseu, j - 1));
            }
            if (maskNE >> 31) {                      // NE of bit31 = word w-7 bit0
                merge_labels(L, rs_of(cur, base, 31), baseu + 32);
                maskNE &= 0x7FFFFFFFu;
            }
            while (maskNE) {
                int j = __ffs(maskNE) - 1; maskNE &= maskNE - 1;
                merge_labels(L, rs_of(cur, base, j), rs_of(up, baseu, j + 1));
            }
        }
    }
    __syncthreads();

    // ---------- Phase C: root-flatten RUN-START entries ----------
    #pragma unroll
    for (int wi = 0; wi < WPT; ++wi) {
        const int w = t + wi * NT;
        unsigned cur = fgw[w];
        unsigned rsm = cur & ~(cur << 1);
        const unsigned base = (unsigned)w << 5;
        while (rsm) {
            int j = __ffs(rsm) - 1; rsm &= rsm - 1;
            unsigned a = base + j;
            unsigned r = find_halve(L, a);
            L[a] = (unsigned short)r;
        }
    }
    __syncthreads();

    // ---------- Phase D: per-pixel areas via L[runstart] (round-4 verbatim) ----------
    #pragma unroll 2
    for (int i = 0; i < PPT; ++i) {
        int p = t + i * NT;
        unsigned word = fgw[p >> 5];                  // warp-uniform: broadcast
        bool fg = (word >> lane) & 1u;
        unsigned zb = ~word & (lane ? ((1u << lane) - 1u) : 0u);
        unsigned rs = zb ? (32u - (unsigned)__clz(zb)) : 0u;
        unsigned root = fg ? (unsigned)L[(p & ~31) + rs] : BGLAB;
        unsigned mm = __match_any_sync(0xFFFFFFFFu, root);
        if (root != BGLAB && lane == (__ffs(mm) - 1))
            atomicAdd(&area[root], __popc(mm));
    }
    __threadfence();
    __syncthreads();

    // ---------- Phase E: top-2 over roots (+bg), read-then-rezero (round-4) ----------
    unsigned long long k1 = 0, k2 = 0;
    #pragma unroll
    for (int wi = 0; wi < WPT; ++wi) {
        const int w = t + wi * NT;
        const unsigned cur = fgw[w];
        unsigned starts = cur & ~(cur << 1);
        const unsigned base = (unsigned)w << 5;
        while (starts) {
            int j = __ffs(starts) - 1; starts &= starts - 1;
            unsigned idx = base + j;
            if (L[idx] == (unsigned short)idx) {      // root
                unsigned a = (unsigned)__ldcg(&area[idx]);
                __stcg(&area[idx], 0);                // restore zero (owner-only)
                unsigned long long k = ((unsigned long long)a << 17) | (0x1FFFFu - idx);
                if (k > k1) { k2 = k1; k1 = k; } else if (k > k2) k2 = k;
            }
        }
    }
    if (t == 0) {
        unsigned bg = (unsigned)(NPIX - s_misc[1]);
        unsigned long long k = ((unsigned long long)bg << 17) | (0x1FFFFu - BGLAB);
        if (k > k1) { k2 = k1; k1 = k; } else if (k > k2) k2 = k;
    }
    for (int o = 16; o; o >>= 1) {
        unsigned long long o1 = __shfl_down_sync(0xFFFFFFFFu, k1, o);
        unsigned long long o2 = __shfl_down_sync(0xFFFFFFFFu, k2, o);
        top2_merge(k1, k2, o1, o2);
    }
    if (lane == 0) { s_top[warp * 2] = k1; s_top[warp * 2 + 1] = k2; }
    __syncthreads();
    if (warp == 0) {
        k1 = s_top[lane * 2];
        k2 = s_top[lane * 2 + 1];
        for (int o = 16; o; o >>= 1) {
            unsigned long long o1 = __shfl_down_sync(0xFFFFFFFFu, k1, o);
            unsigned long long o2 = __shfl_down_sync(0xFFFFFFFFu, k2, o);
            top2_merge(k1, k2, o1, o2);
        }
        if (lane == 0)
            s_misc[0] = (int)(0x1FFFFu - (unsigned)(k2 & 0x1FFFFu));
    }
    __syncthreads();
    const int second = s_misc[0];

    // ---------- Phase F: per-pixel bbox of (lab == second) (round-4 verbatim) ----------
    {
        int mnr = HH, mxr = -1, mnc = WW, mxc = -1;
        #pragma unroll 2
        for (int i = 0; i < PPT; ++i) {
            int p = t + i * NT;
            unsigned word = fgw[p >> 5];
            bool fg = (word >> lane) & 1u;
            unsigned zb = ~word & (lane ? ((1u << lane) - 1u) : 0u);
            unsigned rs = zb ? (32u - (unsigned)__clz(zb)) : 0u;
            int lab = fg ? (int)L[(p & ~31) + rs] : (int)BGLAB;
            if (lab == second) {
                int r = p >> 8, c = p & (WW - 1);
                mnr = min(mnr, r); mxr = max(mxr, r);
                mnc = min(mnc, c); mxc = max(mxc, c);
            }
        }
        if (mxr >= 0) {
            atomicMin(&s_bb[0], mnr); atomicMax(&s_bb[1], mxr);
            atomicMin(&s_bb[2], mnc); atomicMax(&s_bb[3], mxc);
        }
    }
    __syncthreads();
    const int h0 = s_bb[0], h1 = s_bb[1] + 1, w0 = s_bb[2], w1 = s_bb[3] + 1;
    // empty selection => inside always false => pmask == 1 (matches ref)

    // ---------- Phase G: loss = mean(pmask * m), full reload (round-4 verbatim) ----------
    float s = 0.0f;
    #pragma unroll 4
    for (int i = 0; i < PPT; ++i) {
        int p = t + i * NT;
        float x = __ldg(&img[p]);
        float m = fmaxf((x + 1.0f) * 0.5f, 0.0f);
        int r = p >> 8, c = p & (WW - 1);
        bool inside = (r >= h0) & (r < h1) & (c >= w0) & (c < w1);
        if (!inside) s += m;
    }
    for (int o = 16; o; o >>= 1) s += __shfl_down_sync(0xFFFFFFFFu, s, o);
    if (lane == 0) s_wsf[warp] = s;
    __syncthreads();
    if (t == 0) {
        float tot = 0.0f;
        #pragma unroll
        for (int w = 0; w < 32; ++w) tot += s_wsf[w];
        g_loss[b] = tot * (1.0f / (float)NPIX);
    }

    // ---------- last-block final reduction ----------
    __threadfence();
    __syncthreads();
    if (t == 0) {
        unsigned done = atomicAdd(&g_count, 1u);
        s_misc[0] = (done == NIMG - 1) ? 1 : 0;
    }
    __syncthreads();
    if (s_misc[0]) {
        __threadfence();
        if (t < 32) {
            float s2 = __ldcg(&g_loss[t])      + __ldcg(&g_loss[t + 32])
                     + __ldcg(&g_loss[t + 64]) + __ldcg(&g_loss[t + 96]);
            for (int o = 16; o; o >>= 1) s2 += __shfl_down_sync(0xFFFFFFFFu, s2, o);
            if (t == 0) {
                out[0] = s2 * (1.0f / (float)NIMG);
                g_count = 0;
            }
        }
    }
}

extern "C" void kernel_launch(void* const* d_in, const int* in_sizes, int n_in,
                              void* d_out, int out_size) {
    const float* in = (const float*)d_in[0];
    float* out = (float*)d_out;
    (void)in_sizes; (void)n_in; (void)out_size;

    cudaFuncSetAttribute(nlccs_kernel, cudaFuncAttributeMaxDynamicSharedMemorySize, SMEM_BYTES);
    nlccs_kernel<<<NIMG, NT, SMEM_BYTES>>>(in, out);
}